// round 2
// baseline (speedup 1.0000x reference)
#include <cuda_runtime.h>
#include <cuda_bf16.h>

#define N_NODES 100000
#define N_EDGES 1600000
#define D 128
#define N_LAYERS 4

// Scratch (allocation-free rule: __device__ globals)
__device__ float g_agg [N_NODES * D];
__device__ float g_bufA[N_NODES * D];
__device__ float g_bufB[N_NODES * D];
__device__ float g_invdeg[N_NODES];

// ---------------------------------------------------------------------------
// Degree kernels (run once per launch)
// ---------------------------------------------------------------------------
__global__ void deg_kernel(const int* __restrict__ dst, float* __restrict__ deg) {
    int e = blockIdx.x * blockDim.x + threadIdx.x;
    if (e < N_EDGES) atomicAdd(&deg[dst[e]], 1.0f);
}

__global__ void invdeg_kernel(float* __restrict__ deg) {
    int i = blockIdx.x * blockDim.x + threadIdx.x;
    if (i < N_NODES) deg[i] = 1.0f / fmaxf(deg[i], 1.0f);
}

// ---------------------------------------------------------------------------
// Scatter-add: one warp per edge, 32 float4 chunks per row.
// red.global.add.v4.f32: vectorized no-return reduction (sm_90+), 4x fewer
// atomic ops than scalar atomicAdd.
// ---------------------------------------------------------------------------
__global__ void scatter_kernel(const float4* __restrict__ x,
                               const int* __restrict__ src,
                               const int* __restrict__ dst,
                               float4* __restrict__ agg) {
    long long gid = (long long)blockIdx.x * blockDim.x + threadIdx.x;
    int e = (int)(gid >> 5);
    int c = (int)(gid & 31);
    if (e >= N_EDGES) return;
    int s = __ldg(src + e);
    int d = __ldg(dst + e);
    float4 v = __ldg(x + (long long)s * 32 + c);
    float* p = (float*)(agg + (long long)d * 32 + c);
    asm volatile("red.global.add.v4.f32 [%0], {%1, %2, %3, %4};"
                 :: "l"(p), "f"(v.x), "f"(v.y), "f"(v.z), "f"(v.w)
                 : "memory");
}

// ---------------------------------------------------------------------------
// Fused GEMM + bias + ReLU:
//   out[i,j] = relu( sum_k<128  (agg[i,k]*invdeg[i]) * Wl[j,k]
//                  + sum_k<128  x[i,k]               * Wr[j,k]  + bl[j] )
// Block tile: 64 rows x 128 cols (all cols), K=256 in chunks of 32.
// 256 threads: thread t -> colgroup cg=t%32 (4 cols via float4 W),
//                          rowgroup rg=t/32 (8 rows). acc[8][4] in regs.
// ---------------------------------------------------------------------------
#define BK 32
#define WS_STRIDE 132   // [BK][128] padded, float4-aligned reads per k-row
#define AS_STRIDE 36    // [64][BK]  padded, float4-aligned stores

__global__ __launch_bounds__(256, 4)
void gemm_relu_kernel(const float* __restrict__ agg,
                      const float* __restrict__ xin,
                      const float* __restrict__ Wl,
                      const float* __restrict__ bl,
                      const float* __restrict__ Wr,
                      const float* __restrict__ invdeg,
                      float* __restrict__ out) {
    __shared__ float Ws[BK * WS_STRIDE];  // Ws[k][j] = Wcomb[j][kk+k]
    __shared__ float As[64 * AS_STRIDE];  // As[r][k]

    const int t  = threadIdx.x;
    const int cg = t & 31;        // 0..31  -> cols 4*cg..4*cg+3
    const int rg = t >> 5;        // 0..7   -> rows rg*8..rg*8+7
    const int row0 = blockIdx.x * 64;

    float acc[8][4];
#pragma unroll
    for (int r = 0; r < 8; r++)
#pragma unroll
        for (int q = 0; q < 4; q++) acc[r][q] = 0.0f;

    for (int kk = 0; kk < 2 * D; kk += BK) {
        // ---- load W chunk (transposed into smem) ----
#pragma unroll
        for (int i = 0; i < 4; i++) {
            int idx = t + i * 256;        // 0..1023 covers 128 j x 8 kq
            int j  = idx >> 3;            // 0..127
            int kq = idx & 7;             // 0..7 (float4 groups of k)
            int kg = kk + kq * 4;
            const float* wsrc = (kg < D) ? (Wl + j * D + kg)
                                         : (Wr + j * D + (kg - D));
            float4 w = *(const float4*)wsrc;
            int kl = kq * 4;
            Ws[(kl + 0) * WS_STRIDE + j] = w.x;
            Ws[(kl + 1) * WS_STRIDE + j] = w.y;
            Ws[(kl + 2) * WS_STRIDE + j] = w.z;
            Ws[(kl + 3) * WS_STRIDE + j] = w.w;
        }
        // ---- load A chunk ([agg*invdeg | x]) ----
#pragma unroll
        for (int i = 0; i < 2; i++) {
            int idx = t + i * 256;        // 0..511 covers 64 r x 8 kq
            int r  = idx >> 3;            // 0..63
            int kq = idx & 7;
            int row = row0 + r;
            int rc = row < N_NODES ? row : N_NODES - 1;
            int kg = kk + kq * 4;
            float4 a;
            if (kg < D) {
                a = *(const float4*)(agg + (long long)rc * D + kg);
                float s = invdeg[rc];
                a.x *= s; a.y *= s; a.z *= s; a.w *= s;
            } else {
                a = *(const float4*)(xin + (long long)rc * D + (kg - D));
            }
            *(float4*)(As + r * AS_STRIDE + kq * 4) = a;
        }
        __syncthreads();

        // ---- compute ----
#pragma unroll
        for (int k = 0; k < BK; k++) {
            float4 w = *(const float4*)(Ws + k * WS_STRIDE + 4 * cg);
#pragma unroll
            for (int r = 0; r < 8; r++) {
                float a = As[(rg * 8 + r) * AS_STRIDE + k];
                acc[r][0] += a * w.x;
                acc[r][1] += a * w.y;
                acc[r][2] += a * w.z;
                acc[r][3] += a * w.w;
            }
        }
        __syncthreads();
    }

    // ---- epilogue: bias + relu + store ----
    float4 b = *(const float4*)(bl + 4 * cg);
#pragma unroll
    for (int r = 0; r < 8; r++) {
        int row = row0 + rg * 8 + r;
        if (row < N_NODES) {
            float4 o;
            o.x = fmaxf(acc[r][0] + b.x, 0.0f);
            o.y = fmaxf(acc[r][1] + b.y, 0.0f);
            o.z = fmaxf(acc[r][2] + b.z, 0.0f);
            o.w = fmaxf(acc[r][3] + b.w, 0.0f);
            *(float4*)(out + (long long)row * D + 4 * cg) = o;
        }
    }
}

// ---------------------------------------------------------------------------
// kernel_launch
// ---------------------------------------------------------------------------
extern "C" void kernel_launch(void* const* d_in, const int* in_sizes, int n_in,
                              void* d_out, int out_size) {
    const float* x  = (const float*)d_in[0];
    const int*   ei = (const int*)  d_in[1];
    const float* Wl = (const float*)d_in[2];
    const float* bl = (const float*)d_in[3];
    const float* Wr = (const float*)d_in[4];
    float* out = (float*)d_out;

    const int* src = ei;
    const int* dst = ei + N_EDGES;

    float *agg, *bufA, *bufB, *invdeg;
    cudaGetSymbolAddress((void**)&agg,    g_agg);
    cudaGetSymbolAddress((void**)&bufA,   g_bufA);
    cudaGetSymbolAddress((void**)&bufB,   g_bufB);
    cudaGetSymbolAddress((void**)&invdeg, g_invdeg);

    // degree -> inv_deg (once; edges fixed)
    cudaMemsetAsync(invdeg, 0, N_NODES * sizeof(float));
    deg_kernel<<<(N_EDGES + 255) / 256, 256>>>(dst, invdeg);
    invdeg_kernel<<<(N_NODES + 255) / 256, 256>>>(invdeg);

    const long long scat_threads = (long long)N_EDGES * 32;
    const int scat_blocks = (int)((scat_threads + 255) / 256);
    const int gemm_blocks = (N_NODES + 63) / 64;

    const float* cur = x;
    float* outs[N_LAYERS] = {bufA, bufB, bufA, out};

    for (int l = 0; l < N_LAYERS; l++) {
        cudaMemsetAsync(agg, 0, (size_t)N_NODES * D * sizeof(float));
        scatter_kernel<<<scat_blocks, 256>>>((const float4*)cur, src, dst,
                                             (float4*)agg);
        gemm_relu_kernel<<<gemm_blocks, 256>>>(agg, cur,
                                               Wl + (size_t)l * D * D,
                                               bl + (size_t)l * D,
                                               Wr + (size_t)l * D * D,
                                               invdeg, outs[l]);
        cur = outs[l];
    }
}

// round 3
// speedup vs baseline: 1.5821x; 1.5821x over previous
#include <cuda_runtime.h>
#include <cuda_bf16.h>
#include <cstdint>

#define N_NODES 100000
#define N_EDGES 1600000
#define D 128
#define N_LAYERS 4

// ---------------- scratch (__device__ globals; no allocation) ----------------
__device__ float g_agg [N_NODES * D];
__device__ float g_bufA[N_NODES * D];
__device__ float g_bufB[N_NODES * D];
__device__ float g_invdeg[N_NODES];
__device__ int   g_deg   [N_NODES];
__device__ int   g_cursor[N_NODES];
__device__ int   g_rowstart[N_NODES + 1];
__device__ int   g_csr_src[N_EDGES];

// ---------------------------------------------------------------------------
// CSR build (once per launch)
// ---------------------------------------------------------------------------
__global__ void deg_kernel(const int* __restrict__ dst, int* __restrict__ deg) {
    int e = blockIdx.x * blockDim.x + threadIdx.x;
    if (e < N_EDGES) atomicAdd(&deg[dst[e]], 1);
}

// single-block scan over 100K degrees -> row_start (+ invdeg)
__global__ void scan_kernel(const int* __restrict__ deg,
                            int* __restrict__ row_start,
                            float* __restrict__ invdeg) {
    __shared__ int sm[1024];
    const int t = threadIdx.x;
    const int CH = (N_NODES + 1023) / 1024;
    const int base = t * CH;
    int s = 0;
    for (int i = 0; i < CH; i++) {
        int idx = base + i;
        if (idx < N_NODES) s += deg[idx];
    }
    sm[t] = s;
    __syncthreads();
    // inclusive Hillis-Steele
    for (int d = 1; d < 1024; d <<= 1) {
        int v = (t >= d) ? sm[t - d] : 0;
        __syncthreads();
        sm[t] += v;
        __syncthreads();
    }
    int off = sm[t] - s;  // exclusive prefix for this chunk
    for (int i = 0; i < CH; i++) {
        int idx = base + i;
        if (idx < N_NODES) {
            row_start[idx] = off;
            int dg = deg[idx];
            off += dg;
            invdeg[idx] = 1.0f / fmaxf((float)dg, 1.0f);
        }
    }
    if (t == 1023) row_start[N_NODES] = off;
}

__global__ void fill_kernel(const int* __restrict__ src,
                            const int* __restrict__ dst,
                            const int* __restrict__ row_start,
                            int* __restrict__ cursor,
                            int* __restrict__ csr_src) {
    int e = blockIdx.x * blockDim.x + threadIdx.x;
    if (e < N_EDGES) {
        int d = dst[e];
        int p = atomicAdd(&cursor[d], 1);
        csr_src[row_start[d] + p] = src[e];
    }
}

// ---------------------------------------------------------------------------
// Gather-mean: one warp per node, lane owns one float4 column chunk.
// agg written already scaled by invdeg.
// ---------------------------------------------------------------------------
__global__ __launch_bounds__(256)
void gather_kernel(const float4* __restrict__ x4,
                   const int* __restrict__ csr_src,
                   const int* __restrict__ row_start,
                   const float* __restrict__ invdeg,
                   float4* __restrict__ agg4) {
    int warp = (blockIdx.x * blockDim.x + threadIdx.x) >> 5;
    int lane = threadIdx.x & 31;
    if (warp >= N_NODES) return;
    int b = row_start[warp];
    int e = row_start[warp + 1];
    float4 acc = make_float4(0.f, 0.f, 0.f, 0.f);
    for (int j = b; j < e; j += 32) {
        int cnt = min(32, e - j);
        int sreg = (lane < cnt) ? csr_src[j + lane] : 0;
        for (int i = 0; i < cnt; i++) {
            int si = __shfl_sync(0xffffffffu, sreg, i);
            float4 v = __ldg(x4 + (long long)si * 32 + lane);
            acc.x += v.x; acc.y += v.y; acc.z += v.z; acc.w += v.w;
        }
    }
    float sc = invdeg[warp];
    acc.x *= sc; acc.y *= sc; acc.z *= sc; acc.w *= sc;
    agg4[(long long)warp * 32 + lane] = acc;
}

// ---------------------------------------------------------------------------
// 3xTF32 tensor-core GEMM + bias + ReLU
//   out[i,j] = relu( sum_k agg[i,k]*Wl[j,k] + sum_k x[i,k]*Wr[j,k] + bl[j] )
// Block: 64 rows x 128 cols, K=256 in chunks of 32. 8 warps, warp tile 16x64.
// ---------------------------------------------------------------------------
#define KC 32
#define SA 36
#define SB 36

__device__ __forceinline__ void split_tf32(float x, uint32_t& hi, uint32_t& lo) {
    uint32_t h;
    asm("cvt.rna.tf32.f32 %0, %1;" : "=r"(h) : "f"(x));
    float r = x - __uint_as_float(h);
    uint32_t l;
    asm("cvt.rna.tf32.f32 %0, %1;" : "=r"(l) : "f"(r));
    hi = h; lo = l;
}

__device__ __forceinline__ void mma_tf32(float c[4], const uint32_t a[4],
                                         uint32_t b0, uint32_t b1) {
    asm volatile(
        "mma.sync.aligned.m16n8k8.row.col.f32.tf32.tf32.f32 "
        "{%0,%1,%2,%3}, {%4,%5,%6,%7}, {%8,%9}, {%0,%1,%2,%3};"
        : "+f"(c[0]), "+f"(c[1]), "+f"(c[2]), "+f"(c[3])
        : "r"(a[0]), "r"(a[1]), "r"(a[2]), "r"(a[3]), "r"(b0), "r"(b1));
}

__global__ __launch_bounds__(256, 2)
void gemm_relu_kernel(const float* __restrict__ agg,
                      const float* __restrict__ xin,
                      const float* __restrict__ Wl,
                      const float* __restrict__ bl,
                      const float* __restrict__ Wr,
                      float* __restrict__ out) {
    __shared__ float As[64 * SA];
    __shared__ float Bs[128 * SB];

    const int t = threadIdx.x;
    const int lane = t & 31;
    const int w = t >> 5;
    const int wr = (w >> 1) * 16;   // warp row offset in tile
    const int wc = (w & 1) * 64;    // warp col offset
    const int qr = lane >> 2;       // 0..7
    const int qc = lane & 3;        // 0..3
    const int row0 = blockIdx.x * 64;

    float c[8][4];
#pragma unroll
    for (int na = 0; na < 8; na++)
#pragma unroll
        for (int q = 0; q < 4; q++) c[na][q] = 0.0f;

    for (int kk = 0; kk < 2 * D; kk += KC) {
        // load A chunk: 64 rows x 32 k  (agg is pre-scaled; [agg | xin])
#pragma unroll
        for (int i = 0; i < 2; i++) {
            int slot = t + i * 256;          // 0..511
            int r  = slot >> 3;              // 0..63
            int kq = slot & 7;               // 0..7
            int row = row0 + r;
            int rc = row < N_NODES ? row : N_NODES - 1;
            int kg = kk + kq * 4;
            float4 a;
            if (kg < D) a = *(const float4*)(agg + (long long)rc * D + kg);
            else        a = *(const float4*)(xin + (long long)rc * D + (kg - D));
            *(float4*)(As + r * SA + kq * 4) = a;
        }
        // load B chunk: 128 j x 32 k  ([Wl | Wr], row-major in k)
#pragma unroll
        for (int i = 0; i < 4; i++) {
            int slot = t + i * 256;          // 0..1023
            int j  = slot >> 3;              // 0..127
            int kq = slot & 7;
            int kg = kk + kq * 4;
            const float* wsrc = (kg < D) ? (Wl + j * D + kg)
                                         : (Wr + j * D + (kg - D));
            float4 wv = *(const float4*)wsrc;
            *(float4*)(Bs + j * SB + kq * 4) = wv;
        }
        __syncthreads();

#pragma unroll
        for (int k8 = 0; k8 < 4; k8++) {
            int k0 = k8 * 8;
            float a0 = As[(wr + qr) * SA + k0 + qc];
            float a1 = As[(wr + qr + 8) * SA + k0 + qc];
            float a2 = As[(wr + qr) * SA + k0 + qc + 4];
            float a3 = As[(wr + qr + 8) * SA + k0 + qc + 4];
            uint32_t ah[4], al[4];
            split_tf32(a0, ah[0], al[0]);
            split_tf32(a1, ah[1], al[1]);
            split_tf32(a2, ah[2], al[2]);
            split_tf32(a3, ah[3], al[3]);
#pragma unroll
            for (int na = 0; na < 8; na++) {
                float b0 = Bs[(wc + na * 8 + qr) * SB + k0 + qc];
                float b1 = Bs[(wc + na * 8 + qr) * SB + k0 + qc + 4];
                uint32_t bh0, bl0, bh1, bl1;
                split_tf32(b0, bh0, bl0);
                split_tf32(b1, bh1, bl1);
                mma_tf32(c[na], ah, bh0, bh1);  // hi*hi
                mma_tf32(c[na], ah, bl0, bl1);  // hi*lo
                mma_tf32(c[na], al, bh0, bh1);  // lo*hi
            }
        }
        __syncthreads();
    }

    // epilogue: bias + relu + store (thread owns 2x2 per atom)
    int r0 = row0 + wr + qr;
    int r1 = r0 + 8;
#pragma unroll
    for (int na = 0; na < 8; na++) {
        int col = wc + na * 8 + 2 * qc;
        float b0 = bl[col], b1 = bl[col + 1];
        if (r0 < N_NODES) {
            float2 o0;
            o0.x = fmaxf(c[na][0] + b0, 0.0f);
            o0.y = fmaxf(c[na][1] + b1, 0.0f);
            *(float2*)(out + (long long)r0 * D + col) = o0;
        }
        if (r1 < N_NODES) {
            float2 o1;
            o1.x = fmaxf(c[na][2] + b0, 0.0f);
            o1.y = fmaxf(c[na][3] + b1, 0.0f);
            *(float2*)(out + (long long)r1 * D + col) = o1;
        }
    }
}

// ---------------------------------------------------------------------------
// kernel_launch
// ---------------------------------------------------------------------------
extern "C" void kernel_launch(void* const* d_in, const int* in_sizes, int n_in,
                              void* d_out, int out_size) {
    const float* x  = (const float*)d_in[0];
    const int*   ei = (const int*)  d_in[1];
    const float* Wl = (const float*)d_in[2];
    const float* bl = (const float*)d_in[3];
    const float* Wr = (const float*)d_in[4];
    float* out = (float*)d_out;

    const int* src = ei;
    const int* dst = ei + N_EDGES;

    float *agg, *bufA, *bufB, *invdeg;
    int *deg, *cursor, *rowstart, *csr_src;
    cudaGetSymbolAddress((void**)&agg,      g_agg);
    cudaGetSymbolAddress((void**)&bufA,     g_bufA);
    cudaGetSymbolAddress((void**)&bufB,     g_bufB);
    cudaGetSymbolAddress((void**)&invdeg,   g_invdeg);
    cudaGetSymbolAddress((void**)&deg,      g_deg);
    cudaGetSymbolAddress((void**)&cursor,   g_cursor);
    cudaGetSymbolAddress((void**)&rowstart, g_rowstart);
    cudaGetSymbolAddress((void**)&csr_src,  g_csr_src);

    // ---- CSR build (edges fixed; runs once per launch) ----
    cudaMemsetAsync(deg,    0, N_NODES * sizeof(int));
    cudaMemsetAsync(cursor, 0, N_NODES * sizeof(int));
    deg_kernel<<<(N_EDGES + 255) / 256, 256>>>(dst, deg);
    scan_kernel<<<1, 1024>>>(deg, rowstart, invdeg);
    fill_kernel<<<(N_EDGES + 255) / 256, 256>>>(src, dst, rowstart, cursor, csr_src);

    const int gather_blocks = (N_NODES * 32 + 255) / 256;
    const int gemm_blocks = (N_NODES + 63) / 64;

    const float* cur = x;
    float* outs[N_LAYERS] = {bufA, bufB, bufA, out};

    for (int l = 0; l < N_LAYERS; l++) {
        gather_kernel<<<gather_blocks, 256>>>((const float4*)cur, csr_src,
                                              rowstart, invdeg, (float4*)agg);
        gemm_relu_kernel<<<gemm_blocks, 256>>>(agg, cur,
                                               Wl + (size_t)l * D * D,
                                               bl + (size_t)l * D,
                                               Wr + (size_t)l * D * D,
                                               outs[l]);
        cur = outs[l];
    }
}

// round 5
// speedup vs baseline: 1.6755x; 1.0591x over previous
#include <cuda_runtime.h>
#include <cuda_bf16.h>
#include <cstdint>

#define N_NODES 100000
#define N_EDGES 1600000
#define D 128
#define N_LAYERS 4

// ---------------- scratch (__device__ globals; no allocation) ----------------
__device__ float g_agg [N_NODES * D];
__device__ float g_bufA[N_NODES * D];
__device__ float g_bufB[N_NODES * D];
__device__ float g_invdeg[N_NODES];
__device__ int   g_deg   [N_NODES];
__device__ int   g_cursor[N_NODES];
__device__ int   g_rowstart[N_NODES + 1];
__device__ int   g_csr_src[N_EDGES];
// Pre-split weights: combined [l][j][k], k<128 -> Wl, k>=128 -> Wr, tf32 hi/lo
__device__ uint32_t g_Whi[N_LAYERS * D * 2 * D];
__device__ uint32_t g_Wlo[N_LAYERS * D * 2 * D];

__device__ __forceinline__ void split_tf32(float x, uint32_t& hi, uint32_t& lo) {
    uint32_t h;
    asm("cvt.rna.tf32.f32 %0, %1;" : "=r"(h) : "f"(x));
    float r = x - __uint_as_float(h);
    uint32_t l;
    asm("cvt.rna.tf32.f32 %0, %1;" : "=r"(l) : "f"(r));
    hi = h; lo = l;
}

// ---------------------------------------------------------------------------
// Pre-split W into tf32 hi/lo (once per launch)
// ---------------------------------------------------------------------------
__global__ void split_w_kernel(const float* __restrict__ Wl,
                               const float* __restrict__ Wr,
                               uint32_t* __restrict__ Whi,
                               uint32_t* __restrict__ Wlo) {
    int idx = blockIdx.x * blockDim.x + threadIdx.x;   // [l][j][k256]
    if (idx >= N_LAYERS * D * 2 * D) return;
    int k = idx & (2 * D - 1);
    int j = (idx >> 8) & (D - 1);
    int l = idx >> 15;
    float w = (k < D) ? Wl[(l * D + j) * D + k]
                      : Wr[(l * D + j) * D + (k - D)];
    split_tf32(w, Whi[idx], Wlo[idx]);
}

// ---------------------------------------------------------------------------
// CSR build (once per launch)
// ---------------------------------------------------------------------------
__global__ void deg_kernel(const int* __restrict__ dst, int* __restrict__ deg) {
    int e = blockIdx.x * blockDim.x + threadIdx.x;
    if (e < N_EDGES) atomicAdd(&deg[dst[e]], 1);
}

__global__ void scan_kernel(const int* __restrict__ deg,
                            int* __restrict__ row_start,
                            float* __restrict__ invdeg) {
    __shared__ int sm[1024];
    const int t = threadIdx.x;
    const int CH = (N_NODES + 1023) / 1024;
    const int base = t * CH;
    int s = 0;
    for (int i = 0; i < CH; i++) {
        int idx = base + i;
        if (idx < N_NODES) s += deg[idx];
    }
    sm[t] = s;
    __syncthreads();
    for (int d = 1; d < 1024; d <<= 1) {
        int v = (t >= d) ? sm[t - d] : 0;
        __syncthreads();
        sm[t] += v;
        __syncthreads();
    }
    int off = sm[t] - s;
    for (int i = 0; i < CH; i++) {
        int idx = base + i;
        if (idx < N_NODES) {
            row_start[idx] = off;
            int dg = deg[idx];
            off += dg;
            invdeg[idx] = 1.0f / fmaxf((float)dg, 1.0f);
        }
    }
    if (t == 1023) row_start[N_NODES] = off;
}

__global__ void fill_kernel(const int* __restrict__ src,
                            const int* __restrict__ dst,
                            const int* __restrict__ row_start,
                            int* __restrict__ cursor,
                            int* __restrict__ csr_src) {
    int e = blockIdx.x * blockDim.x + threadIdx.x;
    if (e < N_EDGES) {
        int d = dst[e];
        int p = atomicAdd(&cursor[d], 1);
        csr_src[row_start[d] + p] = src[e];
    }
}

// ---------------------------------------------------------------------------
// Gather-mean: one warp per node, lane owns one float4 column chunk.
// ---------------------------------------------------------------------------
__global__ __launch_bounds__(256)
void gather_kernel(const float4* __restrict__ x4,
                   const int* __restrict__ csr_src,
                   const int* __restrict__ row_start,
                   const float* __restrict__ invdeg,
                   float4* __restrict__ agg4) {
    int warp = (blockIdx.x * blockDim.x + threadIdx.x) >> 5;
    int lane = threadIdx.x & 31;
    if (warp >= N_NODES) return;
    int b = row_start[warp];
    int e = row_start[warp + 1];
    float4 acc = make_float4(0.f, 0.f, 0.f, 0.f);
    for (int j = b; j < e; j += 32) {
        int cnt = min(32, e - j);
        int sreg = (lane < cnt) ? csr_src[j + lane] : 0;
        for (int i = 0; i < cnt; i++) {
            int si = __shfl_sync(0xffffffffu, sreg, i);
            float4 v = __ldg(x4 + (long long)si * 32 + lane);
            acc.x += v.x; acc.y += v.y; acc.z += v.z; acc.w += v.w;
        }
    }
    float sc = invdeg[warp];
    acc.x *= sc; acc.y *= sc; acc.z *= sc; acc.w *= sc;
    agg4[(long long)warp * 32 + lane] = acc;
}

// ---------------------------------------------------------------------------
// 3xTF32 tensor-core GEMM + bias + ReLU. No cvt in hot loop:
// W pre-split globally; A split once at smem-store time.
// Block: 64 rows x 128 cols, K=256 in KC=32 chunks. 8 warps, warp 16x64.
// ---------------------------------------------------------------------------
#define KC 32
#define SA 36
#define SB 36

__device__ __forceinline__ void mma_tf32(float c[4], const uint32_t a[4],
                                         uint32_t b0, uint32_t b1) {
    asm volatile(
        "mma.sync.aligned.m16n8k8.row.col.f32.tf32.tf32.f32 "
        "{%0,%1,%2,%3}, {%4,%5,%6,%7}, {%8,%9}, {%0,%1,%2,%3};"
        : "+f"(c[0]), "+f"(c[1]), "+f"(c[2]), "+f"(c[3])
        : "r"(a[0]), "r"(a[1]), "r"(a[2]), "r"(a[3]), "r"(b0), "r"(b1));
}

__global__ __launch_bounds__(256, 2)
void gemm_relu_kernel(const float* __restrict__ agg,
                      const float* __restrict__ xin,
                      const uint32_t* __restrict__ Whi,   // [128][256] this layer
                      const uint32_t* __restrict__ Wlo,
                      const float* __restrict__ bl,
                      float* __restrict__ out) {
    extern __shared__ uint32_t smem[];
    uint32_t* Ah = smem;                    // [64][SA]
    uint32_t* Al = Ah + 64 * SA;
    uint32_t* Bh = Al + 64 * SA;            // [128][SB]
    uint32_t* Bl = Bh + 128 * SB;

    const int t = threadIdx.x;
    const int lane = t & 31;
    const int w = t >> 5;
    const int wr = (w >> 1) * 16;
    const int wc = (w & 1) * 64;
    const int qr = lane >> 2;       // 0..7
    const int qc = lane & 3;        // 0..3
    const int row0 = blockIdx.x * 64;

    float c[8][4];
#pragma unroll
    for (int na = 0; na < 8; na++)
#pragma unroll
        for (int q = 0; q < 4; q++) c[na][q] = 0.0f;

    for (int kk = 0; kk < 2 * D; kk += KC) {
        // ---- A chunk: load float4, split to tf32 hi/lo, store both ----
#pragma unroll
        for (int i = 0; i < 2; i++) {
            int slot = t + i * 256;          // 0..511
            int r  = slot >> 3;              // 0..63
            int kq = slot & 7;               // 0..7
            int row = row0 + r;
            int rc = row < N_NODES ? row : N_NODES - 1;
            int kg = kk + kq * 4;
            float4 a;
            if (kg < D) a = *(const float4*)(agg + (long long)rc * D + kg);
            else        a = *(const float4*)(xin + (long long)rc * D + (kg - D));
            uint4 h, l;
            split_tf32(a.x, h.x, l.x);
            split_tf32(a.y, h.y, l.y);
            split_tf32(a.z, h.z, l.z);
            split_tf32(a.w, h.w, l.w);
            *(uint4*)(Ah + r * SA + kq * 4) = h;
            *(uint4*)(Al + r * SA + kq * 4) = l;
        }
        // ---- B chunk: straight copy of pre-split W ----
#pragma unroll
        for (int i = 0; i < 4; i++) {
            int slot = t + i * 256;          // 0..1023
            int j  = slot >> 3;              // 0..127
            int kq = slot & 7;
            int kg = kk + kq * 4;
            uint4 h = *(const uint4*)(Whi + j * (2 * D) + kg);
            uint4 l = *(const uint4*)(Wlo + j * (2 * D) + kg);
            *(uint4*)(Bh + j * SB + kq * 4) = h;
            *(uint4*)(Bl + j * SB + kq * 4) = l;
        }
        __syncthreads();

        // ---- pure LDS + HMMA ----
#pragma unroll
        for (int k8 = 0; k8 < 4; k8++) {
            int k0 = k8 * 8;
            int ar0 = (wr + qr) * SA + k0 + qc;
            int ar1 = (wr + qr + 8) * SA + k0 + qc;
            uint32_t ah[4], al[4];
            ah[0] = Ah[ar0]; ah[1] = Ah[ar1]; ah[2] = Ah[ar0 + 4]; ah[3] = Ah[ar1 + 4];
            al[0] = Al[ar0]; al[1] = Al[ar1]; al[2] = Al[ar0 + 4]; al[3] = Al[ar1 + 4];
#pragma unroll
            for (int na = 0; na < 8; na++) {
                int boff = (wc + na * 8 + qr) * SB + k0 + qc;
                uint32_t bh0 = Bh[boff], bh1 = Bh[boff + 4];
                uint32_t bl0 = Bl[boff], bl1 = Bl[boff + 4];
                mma_tf32(c[na], ah, bh0, bh1);  // hi*hi
                mma_tf32(c[na], ah, bl0, bl1);  // hi*lo
                mma_tf32(c[na], al, bh0, bh1);  // lo*hi
            }
        }
        __syncthreads();
    }

    // ---- epilogue: bias + relu + store ----
    int r0 = row0 + wr + qr;
    int r1 = r0 + 8;
#pragma unroll
    for (int na = 0; na < 8; na++) {
        int col = wc + na * 8 + 2 * qc;
        float b0 = bl[col], b1 = bl[col + 1];
        if (r0 < N_NODES) {
            float2 o0;
            o0.x = fmaxf(c[na][0] + b0, 0.0f);
            o0.y = fmaxf(c[na][1] + b1, 0.0f);
            *(float2*)(out + (long long)r0 * D + col) = o0;
        }
        if (r1 < N_NODES) {
            float2 o1;
            o1.x = fmaxf(c[na][2] + b0, 0.0f);
            o1.y = fmaxf(c[na][3] + b1, 0.0f);
            *(float2*)(out + (long long)r1 * D + col) = o1;
        }
    }
}

// ---------------------------------------------------------------------------
// kernel_launch
// ---------------------------------------------------------------------------
#define GEMM_SMEM ((2 * 64 * SA + 2 * 128 * SB) * 4)

extern "C" void kernel_launch(void* const* d_in, const int* in_sizes, int n_in,
                              void* d_out, int out_size) {
    const float* x  = (const float*)d_in[0];
    const int*   ei = (const int*)  d_in[1];
    const float* Wl = (const float*)d_in[2];
    const float* bl = (const float*)d_in[3];
    const float* Wr = (const float*)d_in[4];
    float* out = (float*)d_out;

    const int* src = ei;
    const int* dst = ei + N_EDGES;

    float *agg, *bufA, *bufB, *invdeg;
    int *deg, *cursor, *rowstart, *csr_src;
    uint32_t *whi, *wlo;
    cudaGetSymbolAddress((void**)&agg,      g_agg);
    cudaGetSymbolAddress((void**)&bufA,     g_bufA);
    cudaGetSymbolAddress((void**)&bufB,     g_bufB);
    cudaGetSymbolAddress((void**)&invdeg,   g_invdeg);
    cudaGetSymbolAddress((void**)&deg,      g_deg);
    cudaGetSymbolAddress((void**)&cursor,   g_cursor);
    cudaGetSymbolAddress((void**)&rowstart, g_rowstart);
    cudaGetSymbolAddress((void**)&csr_src,  g_csr_src);
    cudaGetSymbolAddress((void**)&whi,      g_Whi);
    cudaGetSymbolAddress((void**)&wlo,      g_Wlo);

    static bool attr_done = false;
    if (!attr_done) {
        cudaFuncSetAttribute(gemm_relu_kernel,
                             cudaFuncAttributeMaxDynamicSharedMemorySize,
                             GEMM_SMEM);
        attr_done = true;
    }

    // ---- one-time preprocessing (deterministic, every launch) ----
    cudaMemsetAsync(deg,    0, N_NODES * sizeof(int));
    cudaMemsetAsync(cursor, 0, N_NODES * sizeof(int));
    deg_kernel<<<(N_EDGES + 255) / 256, 256>>>(dst, deg);
    scan_kernel<<<1, 1024>>>(deg, rowstart, invdeg);
    fill_kernel<<<(N_EDGES + 255) / 256, 256>>>(src, dst, rowstart, cursor, csr_src);
    split_w_kernel<<<(N_LAYERS * D * 2 * D + 255) / 256, 256>>>(Wl, Wr, whi, wlo);

    const int gather_blocks = (N_NODES * 32 + 255) / 256;
    const int gemm_blocks = (N_NODES + 63) / 64;

    const float* cur = x;
    float* outs[N_LAYERS] = {bufA, bufB, bufA, out};

    for (int l = 0; l < N_LAYERS; l++) {
        gather_kernel<<<gather_blocks, 256>>>((const float4*)cur, csr_src,
                                              rowstart, invdeg, (float4*)agg);
        gemm_relu_kernel<<<gemm_blocks, 256, GEMM_SMEM>>>(
            agg, cur,
            whi + (size_t)l * D * 2 * D,
            wlo + (size_t)l * D * 2 * D,
            bl + (size_t)l * D,
            outs[l]);
        cur = outs[l];
    }
}

// round 6
// speedup vs baseline: 1.9139x; 1.1422x over previous
#include <cuda_runtime.h>
#include <cuda_bf16.h>
#include <cstdint>

#define N_NODES 100000
#define N_EDGES 1600000
#define D 128
#define N_LAYERS 4

// ---------------- scratch (__device__ globals; no allocation) ----------------
__device__ float g_agg [N_NODES * D];
__device__ float g_bufA[N_NODES * D];
__device__ float g_bufB[N_NODES * D];
__device__ float g_invdeg[N_NODES];
__device__ int   g_deg   [N_NODES];
__device__ int   g_cursor[N_NODES];
__device__ int   g_rowstart[N_NODES + 1];
__device__ int   g_csr_src[N_EDGES];
// Pre-split packed bf16-pair weights: [l][j][k2], k2 = k/2 over combined K=256
// (k<128 -> Wl, k>=128 -> Wr). Each uint32 = (bf16 w[2k2+1] << 16) | bf16 w[2k2]
__device__ uint32_t g_Whi[N_LAYERS * D * D];   // 4*128*128
__device__ uint32_t g_Wlo[N_LAYERS * D * D];

__device__ __forceinline__ uint32_t pack_bf16(__nv_bfloat16 lo_k, __nv_bfloat16 hi_k) {
    return ((uint32_t)__bfloat16_as_ushort(hi_k) << 16) |
            (uint32_t)__bfloat16_as_ushort(lo_k);
}

__device__ __forceinline__ void split_bf16(float x, __nv_bfloat16& h, __nv_bfloat16& l) {
    h = __float2bfloat16(x);
    l = __float2bfloat16(x - __bfloat162float(h));
}

// ---------------------------------------------------------------------------
// Pre-split W into packed bf16 hi/lo pairs (once per launch)
// ---------------------------------------------------------------------------
__global__ void split_w_kernel(const float* __restrict__ Wl,
                               const float* __restrict__ Wr,
                               uint32_t* __restrict__ Whi,
                               uint32_t* __restrict__ Wlo) {
    int idx = blockIdx.x * blockDim.x + threadIdx.x;   // [l][j][k2]
    if (idx >= N_LAYERS * D * D) return;
    int k2 = idx & (D - 1);          // 0..127 -> k = 2*k2, 2*k2+1 in [0,256)
    int j  = (idx >> 7) & (D - 1);
    int l  = idx >> 14;
    int k0 = 2 * k2, k1 = 2 * k2 + 1;
    float w0 = (k0 < D) ? Wl[(l * D + j) * D + k0] : Wr[(l * D + j) * D + (k0 - D)];
    float w1 = (k1 < D) ? Wl[(l * D + j) * D + k1] : Wr[(l * D + j) * D + (k1 - D)];
    __nv_bfloat16 h0, l0, h1, l1;
    split_bf16(w0, h0, l0);
    split_bf16(w1, h1, l1);
    Whi[idx] = pack_bf16(h0, h1);
    Wlo[idx] = pack_bf16(l0, l1);
}

// ---------------------------------------------------------------------------
// CSR build (once per launch)
// ---------------------------------------------------------------------------
__global__ void deg_kernel(const int* __restrict__ dst, int* __restrict__ deg) {
    int e = blockIdx.x * blockDim.x + threadIdx.x;
    if (e < N_EDGES) atomicAdd(&deg[dst[e]], 1);
}

__global__ void scan_kernel(const int* __restrict__ deg,
                            int* __restrict__ row_start,
                            float* __restrict__ invdeg) {
    __shared__ int sm[1024];
    const int t = threadIdx.x;
    const int CH = (N_NODES + 1023) / 1024;
    const int base = t * CH;
    int s = 0;
    for (int i = 0; i < CH; i++) {
        int idx = base + i;
        if (idx < N_NODES) s += deg[idx];
    }
    sm[t] = s;
    __syncthreads();
    for (int d = 1; d < 1024; d <<= 1) {
        int v = (t >= d) ? sm[t - d] : 0;
        __syncthreads();
        sm[t] += v;
        __syncthreads();
    }
    int off = sm[t] - s;
    for (int i = 0; i < CH; i++) {
        int idx = base + i;
        if (idx < N_NODES) {
            row_start[idx] = off;
            int dg = deg[idx];
            off += dg;
            invdeg[idx] = 1.0f / fmaxf((float)dg, 1.0f);
        }
    }
    if (t == 1023) row_start[N_NODES] = off;
}

__global__ void fill_kernel(const int* __restrict__ src,
                            const int* __restrict__ dst,
                            const int* __restrict__ row_start,
                            int* __restrict__ cursor,
                            int* __restrict__ csr_src) {
    int e = blockIdx.x * blockDim.x + threadIdx.x;
    if (e < N_EDGES) {
        int d = dst[e];
        int p = atomicAdd(&cursor[d], 1);
        csr_src[row_start[d] + p] = src[e];
    }
}

// ---------------------------------------------------------------------------
// Gather-mean: one warp per node, lane owns one float4 column chunk.
// ---------------------------------------------------------------------------
__global__ __launch_bounds__(256)
void gather_kernel(const float4* __restrict__ x4,
                   const int* __restrict__ csr_src,
                   const int* __restrict__ row_start,
                   const float* __restrict__ invdeg,
                   float4* __restrict__ agg4) {
    int warp = (blockIdx.x * blockDim.x + threadIdx.x) >> 5;
    int lane = threadIdx.x & 31;
    if (warp >= N_NODES) return;
    int b = row_start[warp];
    int e = row_start[warp + 1];
    float4 acc = make_float4(0.f, 0.f, 0.f, 0.f);
    for (int j = b; j < e; j += 32) {
        int cnt = min(32, e - j);
        int sreg = (lane < cnt) ? csr_src[j + lane] : 0;
        for (int i = 0; i < cnt; i++) {
            int si = __shfl_sync(0xffffffffu, sreg, i);
            float4 v = __ldg(x4 + (long long)si * 32 + lane);
            acc.x += v.x; acc.y += v.y; acc.z += v.z; acc.w += v.w;
        }
    }
    float sc = invdeg[warp];
    acc.x *= sc; acc.y *= sc; acc.z *= sc; acc.w *= sc;
    agg4[(long long)warp * 32 + lane] = acc;
}

// ---------------------------------------------------------------------------
// 3-term bf16-split tensor GEMM + bias + ReLU (m16n8k16, fp32 accum)
//   out = relu([agg | x] @ [Wl | Wr]^T + bl)
// Block: 64 rows x 128 cols, K=256 in KC=32 chunks (2 k16 MMA steps each).
// 8 warps, warp tile 16x64. All operands packed bf16 pairs in smem.
// ---------------------------------------------------------------------------
#define KC 32
#define SAP 20   // row stride in uint32 for A (16 used) -> conflict-free
#define SBP 20   // row stride for B

__device__ __forceinline__ void mma_bf16(float c[4], const uint32_t a[4],
                                         uint32_t b0, uint32_t b1) {
    asm volatile(
        "mma.sync.aligned.m16n8k16.row.col.f32.bf16.bf16.f32 "
        "{%0,%1,%2,%3}, {%4,%5,%6,%7}, {%8,%9}, {%0,%1,%2,%3};"
        : "+f"(c[0]), "+f"(c[1]), "+f"(c[2]), "+f"(c[3])
        : "r"(a[0]), "r"(a[1]), "r"(a[2]), "r"(a[3]), "r"(b0), "r"(b1));
}

__global__ __launch_bounds__(256, 2)
void gemm_relu_kernel(const float* __restrict__ agg,
                      const float* __restrict__ xin,
                      const uint32_t* __restrict__ Whi,   // [128][128 k2] this layer
                      const uint32_t* __restrict__ Wlo,
                      const float* __restrict__ bl,
                      float* __restrict__ out) {
    __shared__ uint32_t Ah[64 * SAP];
    __shared__ uint32_t Al[64 * SAP];
    __shared__ uint32_t Bh[128 * SBP];
    __shared__ uint32_t Bl[128 * SBP];

    const int t = threadIdx.x;
    const int lane = t & 31;
    const int w = t >> 5;
    const int wr = (w >> 1) * 16;
    const int wc = (w & 1) * 64;
    const int qr = lane >> 2;       // 0..7
    const int qc = lane & 3;        // 0..3
    const int row0 = blockIdx.x * 64;

    float c[8][4];
#pragma unroll
    for (int na = 0; na < 8; na++)
#pragma unroll
        for (int q = 0; q < 4; q++) c[na][q] = 0.0f;

    for (int kk = 0; kk < 2 * D; kk += KC) {
        // ---- A chunk: 64 rows x 32 k -> 16 k2. One thread: 8 k (4 k2). ----
        {
            int r  = t >> 2;              // 0..63
            int kq = t & 3;               // 0..3, covers 8 k each
            int row = row0 + r;
            int rc = row < N_NODES ? row : N_NODES - 1;
            int kg = kk + kq * 8;
            float4 a0, a1;
            if (kg < D) {
                a0 = *(const float4*)(agg + (long long)rc * D + kg);
                a1 = *(const float4*)(agg + (long long)rc * D + kg + 4);
            } else {
                a0 = *(const float4*)(xin + (long long)rc * D + (kg - D));
                a1 = *(const float4*)(xin + (long long)rc * D + (kg - D) + 4);
            }
            __nv_bfloat16 h0,l0,h1,l1,h2,l2,h3,l3,h4,l4,h5,l5,h6,l6,h7,l7;
            split_bf16(a0.x, h0, l0); split_bf16(a0.y, h1, l1);
            split_bf16(a0.z, h2, l2); split_bf16(a0.w, h3, l3);
            split_bf16(a1.x, h4, l4); split_bf16(a1.y, h5, l5);
            split_bf16(a1.z, h6, l6); split_bf16(a1.w, h7, l7);
            uint4 ph, pl;
            ph.x = pack_bf16(h0, h1); ph.y = pack_bf16(h2, h3);
            ph.z = pack_bf16(h4, h5); ph.w = pack_bf16(h6, h7);
            pl.x = pack_bf16(l0, l1); pl.y = pack_bf16(l2, l3);
            pl.z = pack_bf16(l4, l5); pl.w = pack_bf16(l6, l7);
            *(uint4*)(Ah + r * SAP + kq * 4) = ph;   // byte addr r*80+kq*16: 16B aligned
            *(uint4*)(Al + r * SAP + kq * 4) = pl;
        }
        // ---- B chunk: 128 j x 16 k2, straight copy of packed W ----
#pragma unroll
        for (int i = 0; i < 2; i++) {
            int slot = t + i * 256;       // 0..511
            int j  = slot >> 2;           // 0..127
            int kq = slot & 3;
            int k2g = (kk >> 1) + kq * 4;
            uint4 h = *(const uint4*)(Whi + j * D + k2g);
            uint4 l = *(const uint4*)(Wlo + j * D + k2g);
            *(uint4*)(Bh + j * SBP + kq * 4) = h;
            *(uint4*)(Bl + j * SBP + kq * 4) = l;
        }
        __syncthreads();

        // ---- 2 k16 steps of pure LDS + HMMA ----
#pragma unroll
        for (int ks = 0; ks < 2; ks++) {
            int k2b = ks * 8;
            int ar0 = (wr + qr) * SAP + k2b + qc;
            int ar1 = (wr + qr + 8) * SAP + k2b + qc;
            uint32_t ah[4], al[4];
            ah[0] = Ah[ar0]; ah[1] = Ah[ar1]; ah[2] = Ah[ar0 + 4]; ah[3] = Ah[ar1 + 4];
            al[0] = Al[ar0]; al[1] = Al[ar1]; al[2] = Al[ar0 + 4]; al[3] = Al[ar1 + 4];
#pragma unroll
            for (int na = 0; na < 8; na++) {
                int boff = (wc + na * 8 + qr) * SBP + k2b + qc;
                uint32_t bh0 = Bh[boff], bh1 = Bh[boff + 4];
                uint32_t bl0 = Bl[boff], bl1 = Bl[boff + 4];
                mma_bf16(c[na], ah, bh0, bh1);  // hi*hi
                mma_bf16(c[na], ah, bl0, bl1);  // hi*lo
                mma_bf16(c[na], al, bh0, bh1);  // lo*hi
            }
        }
        __syncthreads();
    }

    // ---- epilogue: bias + relu + store ----
    int r0 = row0 + wr + qr;
    int r1 = r0 + 8;
#pragma unroll
    for (int na = 0; na < 8; na++) {
        int col = wc + na * 8 + 2 * qc;
        float b0 = bl[col], b1 = bl[col + 1];
        if (r0 < N_NODES) {
            float2 o0;
            o0.x = fmaxf(c[na][0] + b0, 0.0f);
            o0.y = fmaxf(c[na][1] + b1, 0.0f);
            *(float2*)(out + (long long)r0 * D + col) = o0;
        }
        if (r1 < N_NODES) {
            float2 o1;
            o1.x = fmaxf(c[na][2] + b0, 0.0f);
            o1.y = fmaxf(c[na][3] + b1, 0.0f);
            *(float2*)(out + (long long)r1 * D + col) = o1;
        }
    }
}

// ---------------------------------------------------------------------------
// kernel_launch
// ---------------------------------------------------------------------------
extern "C" void kernel_launch(void* const* d_in, const int* in_sizes, int n_in,
                              void* d_out, int out_size) {
    const float* x  = (const float*)d_in[0];
    const int*   ei = (const int*)  d_in[1];
    const float* Wl = (const float*)d_in[2];
    const float* bl = (const float*)d_in[3];
    const float* Wr = (const float*)d_in[4];
    float* out = (float*)d_out;

    const int* src = ei;
    const int* dst = ei + N_EDGES;

    float *agg, *bufA, *bufB, *invdeg;
    int *deg, *cursor, *rowstart, *csr_src;
    uint32_t *whi, *wlo;
    cudaGetSymbolAddress((void**)&agg,      g_agg);
    cudaGetSymbolAddress((void**)&bufA,     g_bufA);
    cudaGetSymbolAddress((void**)&bufB,     g_bufB);
    cudaGetSymbolAddress((void**)&invdeg,   g_invdeg);
    cudaGetSymbolAddress((void**)&deg,      g_deg);
    cudaGetSymbolAddress((void**)&cursor,   g_cursor);
    cudaGetSymbolAddress((void**)&rowstart, g_rowstart);
    cudaGetSymbolAddress((void**)&csr_src,  g_csr_src);
    cudaGetSymbolAddress((void**)&whi,      g_Whi);
    cudaGetSymbolAddress((void**)&wlo,      g_Wlo);

    // ---- one-time preprocessing (deterministic, every launch) ----
    cudaMemsetAsync(deg,    0, N_NODES * sizeof(int));
    cudaMemsetAsync(cursor, 0, N_NODES * sizeof(int));
    deg_kernel<<<(N_EDGES + 255) / 256, 256>>>(dst, deg);
    scan_kernel<<<1, 1024>>>(deg, rowstart, invdeg);
    fill_kernel<<<(N_EDGES + 255) / 256, 256>>>(src, dst, rowstart, cursor, csr_src);
    split_w_kernel<<<(N_LAYERS * D * D + 255) / 256, 256>>>(Wl, Wr, whi, wlo);

    const int gather_blocks = (N_NODES * 32 + 255) / 256;
    const int gemm_blocks = (N_NODES + 63) / 64;

    const float* cur = x;
    float* outs[N_LAYERS] = {bufA, bufB, bufA, out};

    for (int l = 0; l < N_LAYERS; l++) {
        gather_kernel<<<gather_blocks, 256>>>((const float4*)cur, csr_src,
                                              rowstart, invdeg, (float4*)agg);
        gemm_relu_kernel<<<gemm_blocks, 256>>>(
            agg, cur,
            whi + (size_t)l * D * D,
            wlo + (size_t)l * D * D,
            bl + (size_t)l * D,
            outs[l]);
        cur = outs[l];
    }
}

// round 8
// speedup vs baseline: 2.0395x; 1.0656x over previous
#include <cuda_runtime.h>
#include <cuda_bf16.h>
#include <cstdint>

#define N_NODES 100000
#define N_EDGES 1600000
#define D 128
#define N_LAYERS 4
#define ROWU32 128          // 256 bf16 per activation row = 128 uint32

// ---------------- scratch (__device__ globals; no allocation) ----------------
__device__ float g_bufA[N_NODES * D];
__device__ float g_bufB[N_NODES * D];
__device__ float g_invdeg[N_NODES];
__device__ int   g_deg[N_NODES];
__device__ int   g_cursor[N_NODES];
__device__ int   g_rowstart[N_NODES + 1];
__device__ int   g_csr_src[N_EDGES];
// Packed bf16 activations [row][k2]: k2<64 = agg-half, k2>=64 = x-half
__device__ uint32_t g_Ahi[(size_t)N_NODES * ROWU32];
__device__ uint32_t g_Alo[(size_t)N_NODES * ROWU32];
// Packed bf16 weights [l][j][k2] combined (k<128 -> Wl, k>=128 -> Wr)
__device__ uint32_t g_Whi[N_LAYERS * D * ROWU32];
__device__ uint32_t g_Wlo[N_LAYERS * D * ROWU32];

// ------------------------------ helpers -------------------------------------
__device__ __forceinline__ uint32_t smem_u32(const void* p) {
    uint32_t a;
    asm("{ .reg .u64 t; cvta.to.shared.u64 t, %1; cvt.u32.u64 %0, t; }"
        : "=r"(a) : "l"(p));
    return a;
}
__device__ __forceinline__ void cp16(uint32_t saddr, const void* g) {
    asm volatile("cp.async.ca.shared.global [%0], [%1], 16;"
                 :: "r"(saddr), "l"(g) : "memory");
}
#define CP_COMMIT() asm volatile("cp.async.commit_group;" ::: "memory")
#define CP_WAIT(n)  asm volatile("cp.async.wait_group %0;" :: "n"(n) : "memory")

__device__ __forceinline__ uint32_t pack_bf16(__nv_bfloat16 a, __nv_bfloat16 b) {
    return ((uint32_t)__bfloat16_as_ushort(b) << 16) | (uint32_t)__bfloat16_as_ushort(a);
}
__device__ __forceinline__ void split_bf16(float x, __nv_bfloat16& h, __nv_bfloat16& l) {
    h = __float2bfloat16(x);
    l = __float2bfloat16(x - __bfloat162float(h));
}
__device__ __forceinline__ void split4(float4 v, uint2& ph, uint2& pl) {
    __nv_bfloat16 h0, l0, h1, l1, h2, l2, h3, l3;
    split_bf16(v.x, h0, l0); split_bf16(v.y, h1, l1);
    split_bf16(v.z, h2, l2); split_bf16(v.w, h3, l3);
    ph.x = pack_bf16(h0, h1); ph.y = pack_bf16(h2, h3);
    pl.x = pack_bf16(l0, l1); pl.y = pack_bf16(l2, l3);
}

__device__ __forceinline__ void mma_bf16(float c[4], const uint32_t a[4],
                                         uint32_t b0, uint32_t b1) {
    asm volatile(
        "mma.sync.aligned.m16n8k16.row.col.f32.bf16.bf16.f32 "
        "{%0,%1,%2,%3}, {%4,%5,%6,%7}, {%8,%9}, {%0,%1,%2,%3};"
        : "+f"(c[0]), "+f"(c[1]), "+f"(c[2]), "+f"(c[3])
        : "r"(a[0]), "r"(a[1]), "r"(a[2]), "r"(a[3]), "r"(b0), "r"(b1));
}

// ---------------------------------------------------------------------------
// Setup kernels  (launch order engineered so layer-0 GEMM is launch #6)
// ---------------------------------------------------------------------------
__global__ void deg_kernel(const int* __restrict__ dst, int* __restrict__ deg) {
    int e = blockIdx.x * blockDim.x + threadIdx.x;
    if (e < N_EDGES) atomicAdd(&deg[dst[e]], 1);
}

// scan also zeroes cursor (fill runs after)
__global__ void scan_kernel(const int* __restrict__ deg,
                            int* __restrict__ row_start,
                            float* __restrict__ invdeg,
                            int* __restrict__ cursor) {
    __shared__ int sm[1024];
    const int t = threadIdx.x;
    const int CH = (N_NODES + 1023) / 1024;
    const int base = t * CH;
    int s = 0;
    for (int i = 0; i < CH; i++) {
        int idx = base + i;
        if (idx < N_NODES) s += deg[idx];
    }
    sm[t] = s;
    __syncthreads();
    for (int d = 1; d < 1024; d <<= 1) {
        int v = (t >= d) ? sm[t - d] : 0;
        __syncthreads();
        sm[t] += v;
        __syncthreads();
    }
    int off = sm[t] - s;
    for (int i = 0; i < CH; i++) {
        int idx = base + i;
        if (idx < N_NODES) {
            row_start[idx] = off;
            int dg = deg[idx];
            off += dg;
            invdeg[idx] = 1.0f / fmaxf((float)dg, 1.0f);
            cursor[idx] = 0;
        }
    }
    if (t == 1023) row_start[N_NODES] = off;
}

// fill also performs the W hi/lo split (folded to keep launch count down)
__global__ void fill_kernel(const int* __restrict__ src,
                            const int* __restrict__ dst,
                            const int* __restrict__ row_start,
                            int* __restrict__ cursor,
                            int* __restrict__ csr_src,
                            const float* __restrict__ Wl,
                            const float* __restrict__ Wr,
                            uint32_t* __restrict__ Whi,
                            uint32_t* __restrict__ Wlo) {
    int e = blockIdx.x * blockDim.x + threadIdx.x;
    if (e < N_EDGES) {
        int d = dst[e];
        int p = atomicAdd(&cursor[d], 1);
        csr_src[row_start[d] + p] = src[e];
    }
    if (e < N_LAYERS * D * ROWU32) {   // 65536 threads also split W
        int k2 = e & (ROWU32 - 1);
        int j  = (e >> 7) & (D - 1);
        int l  = e >> 14;
        int k0 = 2 * k2, k1 = 2 * k2 + 1;
        float w0 = (k0 < D) ? Wl[(l * D + j) * D + k0] : Wr[(l * D + j) * D + (k0 - D)];
        float w1 = (k1 < D) ? Wl[(l * D + j) * D + k1] : Wr[(l * D + j) * D + (k1 - D)];
        __nv_bfloat16 h0, l0, h1, l1;
        split_bf16(w0, h0, l0);
        split_bf16(w1, h1, l1);
        Whi[e] = pack_bf16(h0, h1);
        Wlo[e] = pack_bf16(l0, l1);
    }
}

// ---------------------------------------------------------------------------
// Gather-mean -> packed bf16 hi/lo agg-half; also splits own x row (x-half).
// One warp per node; lane owns one float4 column chunk.
// ---------------------------------------------------------------------------
__global__ __launch_bounds__(256)
void gather_kernel(const float4* __restrict__ x4,
                   const int* __restrict__ csr_src,
                   const int* __restrict__ row_start,
                   const float* __restrict__ invdeg,
                   uint32_t* __restrict__ Ahi,
                   uint32_t* __restrict__ Alo) {
    int warp = (blockIdx.x * blockDim.x + threadIdx.x) >> 5;
    int lane = threadIdx.x & 31;
    if (warp >= N_NODES) return;
    int b = row_start[warp];
    int e = row_start[warp + 1];
    float4 acc = make_float4(0.f, 0.f, 0.f, 0.f);
    for (int j = b; j < e; j += 32) {
        int cnt = min(32, e - j);
        int sreg = (lane < cnt) ? csr_src[j + lane] : 0;
        for (int i = 0; i < cnt; i++) {
            int si = __shfl_sync(0xffffffffu, sreg, i);
            float4 v = __ldg(x4 + (long long)si * 32 + lane);
            acc.x += v.x; acc.y += v.y; acc.z += v.z; acc.w += v.w;
        }
    }
    float sc = invdeg[warp];
    acc.x *= sc; acc.y *= sc; acc.z *= sc; acc.w *= sc;
    long long rb = (long long)warp * ROWU32;
    uint2 ph, pl;
    split4(acc, ph, pl);
    *(uint2*)(Ahi + rb + lane * 2) = ph;
    *(uint2*)(Alo + rb + lane * 2) = pl;
    // own x row -> x-half
    float4 mine = __ldg(x4 + (long long)warp * 32 + lane);
    split4(mine, ph, pl);
    *(uint2*)(Ahi + rb + 64 + lane * 2) = ph;
    *(uint2*)(Alo + rb + 64 + lane * 2) = pl;
}

// ---------------------------------------------------------------------------
// 3-term bf16 mma.sync GEMM + bias + ReLU.
// CTA tile 128x128, warp tile 32x64 (8 warps). K=256 (128 k2) in 8 chunks of
// 16 k2, cp.async double-buffered. All operands pre-split packed bf16.
// ---------------------------------------------------------------------------
#define SAP 20                        // row stride (uint32); 80B, 16B-aligned
#define ARR_SZ (128 * SAP)            // 2560 uint32 = 10240 B per operand array
#define BUF_SZ (4 * ARR_SZ)           // Ah|Al|Bh|Bl
#define GEMM_SMEM (2 * BUF_SZ * 4)    // 81920 B

__global__ __launch_bounds__(256, 2)
void gemm_relu_kernel(const uint32_t* __restrict__ Ahi,
                      const uint32_t* __restrict__ Alo,
                      const uint32_t* __restrict__ Whi,
                      const uint32_t* __restrict__ Wlo,
                      const float* __restrict__ bl,
                      float* __restrict__ xout) {
    extern __shared__ uint32_t smem[];
    const uint32_t sbase = smem_u32(smem);
    const int t = threadIdx.x;
    const int lane = t & 31;
    const int w = t >> 5;
    const int wr = (w >> 1) * 32;     // warp row offset (4 warps x 32 rows)
    const int wc = (w & 1) * 64;      // warp col offset
    const int qr = lane >> 2;         // 0..7
    const int qc = lane & 3;          // 0..3
    const int row0 = blockIdx.x * 128;

    float c[2][8][4];
#pragma unroll
    for (int ma = 0; ma < 2; ma++)
#pragma unroll
        for (int na = 0; na < 8; na++)
#pragma unroll
            for (int q = 0; q < 4; q++) c[ma][na][q] = 0.0f;

    // per-thread load slots: 8 x 16B cp.async covering Ah|Al|Bh|Bl chunk
    // slot = t + s*256; arr = slot>>9; rem = slot&511; r = rem>>2; g = rem&3
    auto load_chunk = [&](int i, int b) {
        uint32_t bb = sbase + (uint32_t)(b * BUF_SZ * 4);
#pragma unroll
        for (int s = 0; s < 8; s++) {
            int slot = t + s * 256;
            int arr = slot >> 9;
            int rem = slot & 511;
            int r = rem >> 2;
            int g = rem & 3;
            uint32_t saddr = bb + (uint32_t)(arr * ARR_SZ * 4 + r * (SAP * 4) + g * 16);
            const uint32_t* gp;
            if (arr < 2) {
                int rg = row0 + r;
                if (rg >= N_NODES) rg = N_NODES - 1;
                const uint32_t* basep = arr == 0 ? Ahi : Alo;
                gp = basep + (long long)rg * ROWU32 + i * 16 + g * 4;
            } else {
                const uint32_t* basep = arr == 2 ? Whi : Wlo;
                gp = basep + r * ROWU32 + i * 16 + g * 4;
            }
            cp16(saddr, gp);
        }
        CP_COMMIT();
    };

    load_chunk(0, 0);

    for (int i = 0; i < 8; i++) {
        const int b = i & 1;
        if (i < 7) load_chunk(i + 1, b ^ 1);
        if (i < 7) CP_WAIT(1); else CP_WAIT(0);
        __syncthreads();

        const uint32_t* Ah = smem + b * BUF_SZ;
        const uint32_t* Al = Ah + ARR_SZ;
        const uint32_t* Bh = Al + ARR_SZ;
        const uint32_t* Bl = Bh + ARR_SZ;

#pragma unroll
        for (int ks = 0; ks < 2; ks++) {
            const int k2b = ks * 8;
            uint32_t ah[2][4], al[2][4];
#pragma unroll
            for (int ma = 0; ma < 2; ma++) {
                int base = (wr + ma * 16 + qr) * SAP + k2b + qc;
                ah[ma][0] = Ah[base];           al[ma][0] = Al[base];
                ah[ma][1] = Ah[base + 8 * SAP]; al[ma][1] = Al[base + 8 * SAP];
                ah[ma][2] = Ah[base + 4];       al[ma][2] = Al[base + 4];
                ah[ma][3] = Ah[base + 8 * SAP + 4]; al[ma][3] = Al[base + 8 * SAP + 4];
            }
#pragma unroll
            for (int na = 0; na < 8; na++) {
                int boff = (wc + na * 8 + qr) * SAP + k2b + qc;
                uint32_t bh0 = Bh[boff], bh1 = Bh[boff + 4];
                uint32_t bl0 = Bl[boff], bl1 = Bl[boff + 4];
#pragma unroll
                for (int ma = 0; ma < 2; ma++) {
                    mma_bf16(c[ma][na], ah[ma], bh0, bh1);  // hi*hi
                    mma_bf16(c[ma][na], ah[ma], bl0, bl1);  // hi*lo
                    mma_bf16(c[ma][na], al[ma], bh0, bh1);  // lo*hi
                }
            }
        }
        __syncthreads();
    }

    // ---- epilogue: bias + relu + fp32 store ----
#pragma unroll
    for (int na = 0; na < 8; na++) {
        int col = wc + na * 8 + 2 * qc;
        float b0 = __ldg(bl + col), b1 = __ldg(bl + col + 1);
#pragma unroll
        for (int ma = 0; ma < 2; ma++) {
            int r0 = row0 + wr + ma * 16 + qr;
            int r1 = r0 + 8;
            if (r0 < N_NODES) {
                float2 o;
                o.x = fmaxf(c[ma][na][0] + b0, 0.f);
                o.y = fmaxf(c[ma][na][1] + b1, 0.f);
                *(float2*)(xout + (long long)r0 * D + col) = o;
            }
            if (r1 < N_NODES) {
                float2 o;
                o.x = fmaxf(c[ma][na][2] + b0, 0.f);
                o.y = fmaxf(c[ma][na][3] + b1, 0.f);
                *(float2*)(xout + (long long)r1 * D + col) = o;
            }
        }
    }
}

// ---------------------------------------------------------------------------
// kernel_launch — launch order: memset, deg, scan, fill, gather, GEMM(#6)...
// ---------------------------------------------------------------------------
extern "C" void kernel_launch(void* const* d_in, const int* in_sizes, int n_in,
                              void* d_out, int out_size) {
    const float* x  = (const float*)d_in[0];
    const int*   ei = (const int*)  d_in[1];
    const float* Wl = (const float*)d_in[2];
    const float* bl = (const float*)d_in[3];
    const float* Wr = (const float*)d_in[4];
    float* out = (float*)d_out;

    const int* src = ei;
    const int* dst = ei + N_EDGES;

    float *bufA, *bufB, *invdeg;
    int *deg, *cursor, *rowstart, *csr_src;
    uint32_t *ahi, *alo, *whi, *wlo;
    cudaGetSymbolAddress((void**)&bufA,     g_bufA);
    cudaGetSymbolAddress((void**)&bufB,     g_bufB);
    cudaGetSymbolAddress((void**)&invdeg,   g_invdeg);
    cudaGetSymbolAddress((void**)&deg,      g_deg);
    cudaGetSymbolAddress((void**)&cursor,   g_cursor);
    cudaGetSymbolAddress((void**)&rowstart, g_rowstart);
    cudaGetSymbolAddress((void**)&csr_src,  g_csr_src);
    cudaGetSymbolAddress((void**)&ahi,      g_Ahi);
    cudaGetSymbolAddress((void**)&alo,      g_Alo);
    cudaGetSymbolAddress((void**)&whi,      g_Whi);
    cudaGetSymbolAddress((void**)&wlo,      g_Wlo);

    cudaFuncSetAttribute(gemm_relu_kernel,
                         cudaFuncAttributeMaxDynamicSharedMemorySize, GEMM_SMEM);

    cudaMemsetAsync(deg, 0, N_NODES * sizeof(int));                      // #1
    deg_kernel<<<(N_EDGES + 255) / 256, 256>>>(dst, deg);                // #2
    scan_kernel<<<1, 1024>>>(deg, rowstart, invdeg, cursor);             // #3
    fill_kernel<<<(N_EDGES + 255) / 256, 256>>>(src, dst, rowstart,      // #4
                                                cursor, csr_src,
                                                Wl, Wr, whi, wlo);

    const int gather_blocks = (N_NODES * 32 + 255) / 256;
    const int gemm_blocks = (N_NODES + 127) / 128;

    const float* cur = x;
    float* outs[N_LAYERS] = {bufA, bufB, bufA, out};

    for (int l = 0; l < N_LAYERS; l++) {
        gather_kernel<<<gather_blocks, 256>>>((const float4*)cur, csr_src,   // #5
                                              rowstart, invdeg, ahi, alo);
        gemm_relu_kernel<<<gemm_blocks, 256, GEMM_SMEM>>>(                   // #6
            ahi, alo,
            whi + (size_t)l * D * ROWU32,
            wlo + (size_t)l * D * ROWU32,
            bl + (size_t)l * D,
            outs[l]);
        cur = outs[l];
    }
}